// round 9
// baseline (speedup 1.0000x reference)
#include <cuda_runtime.h>
#include <cstdint>

// out[b, 0:128]   = x[b, :]                       for b < B
// out[b, 128:256] = sum_{e: dst[e]==b} x[src[e]]
//
// Pipeline:
//   memset:  zero overflow counter only (4 bytes).
//   K1 bin:  ELL binning (scalar, one edge per thread; src load hoisted so
//            both index loads are in flight together).
//   K2 main: EXACT R4 main-loop shape (ptxas unrolls it ~4x -> MLP~4, the
//            measured best) + one-line self-clean of g_cnt (replaces the
//            200KB memset node). No atomics in the main path.

#define NFEAT   128
#define ROW_OUT 256
#define MAX_E   640000
#define B_MAX   65536
#define SLOTS   32

__device__ int  g_cnt[B_MAX];
__device__ int  g_ell[B_MAX * SLOTS];
__device__ int2 g_ovf[MAX_E];
__device__ int  g_ovf_count;

__global__ void bin_kernel(const int* __restrict__ ei, int E, int B) {
    int i = blockIdx.x * blockDim.x + threadIdx.x;
    if (i >= E) return;
    int d = __ldg(ei + E + i);
    int s = __ldg(ei + i);          // hoisted: issues alongside the d load
    if ((unsigned)d < (unsigned)B) {
        int k = atomicAdd(&g_cnt[d], 1);
        if (k < SLOTS) {
            g_ell[d * SLOTS + k] = s;
        } else {
            int p = atomicAdd(&g_ovf_count, 1);
            g_ovf[p] = make_int2(s, d);
        }
    }
}

__global__ void main_kernel(const float* __restrict__ x,
                            float* __restrict__ out,
                            int B) {
    int warp = (blockIdx.x * blockDim.x + threadIdx.x) >> 5;
    int lane = threadIdx.x & 31;
    if (warp >= B) return;
    int b = warp;

    int c_raw = g_cnt[b];
    int c = c_raw < SLOTS ? c_raw : SLOTS;
    if (lane == 0) g_cnt[b] = 0;    // self-clean (replaces memset node)

    // Coalesced preload of this row's source list (one slot per lane).
    int src_l = (lane < c) ? g_ell[b * SLOTS + lane] : 0;

    float4 acc = make_float4(0.f, 0.f, 0.f, 0.f);
    for (int k = 0; k < c; k++) {
        int se = __shfl_sync(0xFFFFFFFFu, src_l, k);
        float4 v = __ldg(reinterpret_cast<const float4*>(
                             x + (size_t)se * NFEAT) + lane);
        acc.x += v.x; acc.y += v.y; acc.z += v.z; acc.w += v.w;
    }

    // Rare path: degree exceeded SLOTS -> extras live in the overflow list.
    if (c_raw > SLOTS) {
        int n = g_ovf_count;
        for (int e = 0; e < n; e++) {
            int2 ed = g_ovf[e];
            if (ed.y == b) {
                float4 v = __ldg(reinterpret_cast<const float4*>(
                                     x + (size_t)ed.x * NFEAT) + lane);
                acc.x += v.x; acc.y += v.y; acc.z += v.z; acc.w += v.w;
            }
        }
    }

    // Fused: first half = x[b], second half = neighbor sum.
    float4 mine = __ldg(reinterpret_cast<const float4*>(
                            x + (size_t)b * NFEAT) + lane);
    float4* orow = reinterpret_cast<float4*>(out + (size_t)b * ROW_OUT);
    orow[lane]               = mine;
    orow[(NFEAT / 4) + lane] = acc;
}

extern "C" void kernel_launch(void* const* d_in, const int* in_sizes, int n_in,
                              void* d_out, int out_size) {
    const float* x        = (const float*)d_in[0];
    const int*   edge_idx = (const int*)d_in[1];
    float*       out      = (float*)d_out;

    int B = out_size / ROW_OUT;          // 50000
    int E = in_sizes[1] / 2;             // 640000

    // Only the 4-byte overflow counter needs a memset node.
    void* p_ovfc = nullptr;
    cudaGetSymbolAddress(&p_ovfc, g_ovf_count);
    cudaMemsetAsync(p_ovfc, 0, sizeof(int));

    {   // K1: ELL binning (one edge per thread)
        int threads = 256;
        int blocks = (E + threads - 1) / threads;
        bin_kernel<<<blocks, threads>>>(edge_idx, E, B);
    }
    {   // K2: main fused gather-accumulate-store, one full warp per row
        int threads = 256;                          // 8 warps/block
        int blocks = (B + 7) / 8;
        main_kernel<<<blocks, threads>>>(x, out, B);
    }
}

// round 10
// speedup vs baseline: 2.1148x; 2.1148x over previous
#include <cuda_runtime.h>
#include <cstdint>

// out[b, 0:128]   = x[b, :]                       for b < B
// out[b, 128:256] = sum_{e: dst[e]==b} x[src[e]]
//
// Pipeline (all pieces individually measured-good):
//   K0 zero_cnt: zero per-row counters + overflow counter (R3 form, ~1.5us).
//   K1 bin:      ELL binning, scalar one edge/thread (R3 form, ~5us).
//   K2 main:     R4-exact main (27.1us measured): one warp per row, simple
//                gather loop (ptxas unrolls it), in-main overflow scan,
//                NO stores before the gather loop (a pre-loop STG to a
//                device global measurably destroys the loop's load batching).

#define NFEAT   128
#define ROW_OUT 256
#define MAX_E   640000
#define B_MAX   65536
#define SLOTS   32

__device__ int  g_cnt[B_MAX];
__device__ int  g_ell[B_MAX * SLOTS];
__device__ int2 g_ovf[MAX_E];
__device__ int  g_ovf_count;

__global__ void zero_cnt_kernel(int B) {
    int i = blockIdx.x * blockDim.x + threadIdx.x;
    if (i == 0) g_ovf_count = 0;
    if (i < B) g_cnt[i] = 0;
}

__global__ void bin_kernel(const int* __restrict__ ei, int E, int B) {
    int i = blockIdx.x * blockDim.x + threadIdx.x;
    if (i >= E) return;
    int d = __ldg(ei + E + i);
    if ((unsigned)d < (unsigned)B) {
        int s = __ldg(ei + i);
        int k = atomicAdd(&g_cnt[d], 1);
        if (k < SLOTS) {
            g_ell[d * SLOTS + k] = s;
        } else {
            int p = atomicAdd(&g_ovf_count, 1);
            g_ovf[p] = make_int2(s, d);
        }
    }
}

__global__ void main_kernel(const float* __restrict__ x,
                            float* __restrict__ out,
                            int B) {
    int warp = (blockIdx.x * blockDim.x + threadIdx.x) >> 5;
    int lane = threadIdx.x & 31;
    if (warp >= B) return;
    int b = warp;

    int c_raw = g_cnt[b];
    int c = c_raw < SLOTS ? c_raw : SLOTS;

    // Coalesced preload of this row's source list (one slot per lane).
    int src_l = (lane < c) ? g_ell[b * SLOTS + lane] : 0;

    float4 acc = make_float4(0.f, 0.f, 0.f, 0.f);
    for (int k = 0; k < c; k++) {
        int se = __shfl_sync(0xFFFFFFFFu, src_l, k);
        float4 v = __ldg(reinterpret_cast<const float4*>(
                             x + (size_t)se * NFEAT) + lane);
        acc.x += v.x; acc.y += v.y; acc.z += v.z; acc.w += v.w;
    }

    // Rare path: degree exceeded SLOTS -> extras live in the overflow list.
    if (c_raw > SLOTS) {
        int n = g_ovf_count;
        for (int e = 0; e < n; e++) {
            int2 ed = g_ovf[e];
            if (ed.y == b) {
                float4 v = __ldg(reinterpret_cast<const float4*>(
                                     x + (size_t)ed.x * NFEAT) + lane);
                acc.x += v.x; acc.y += v.y; acc.z += v.z; acc.w += v.w;
            }
        }
    }

    // Fused: first half = x[b], second half = neighbor sum.
    float4 mine = __ldg(reinterpret_cast<const float4*>(
                            x + (size_t)b * NFEAT) + lane);
    float4* orow = reinterpret_cast<float4*>(out + (size_t)b * ROW_OUT);
    orow[lane]               = mine;
    orow[(NFEAT / 4) + lane] = acc;
}

extern "C" void kernel_launch(void* const* d_in, const int* in_sizes, int n_in,
                              void* d_out, int out_size) {
    const float* x        = (const float*)d_in[0];
    const int*   edge_idx = (const int*)d_in[1];
    float*       out      = (float*)d_out;

    int B = out_size / ROW_OUT;          // 50000
    int E = in_sizes[1] / 2;             // 640000

    {   // K0: zero counters (kernel, not memset nodes — measured cheaper)
        int threads = 256;
        int blocks = (B + threads - 1) / threads;
        zero_cnt_kernel<<<blocks, threads>>>(B);
    }
    {   // K1: ELL binning (one edge per thread)
        int threads = 256;
        int blocks = (E + threads - 1) / threads;
        bin_kernel<<<blocks, threads>>>(edge_idx, E, B);
    }
    {   // K2: main fused gather-accumulate-store, one full warp per row
        int threads = 256;                          // 8 warps/block
        int blocks = (B + 7) / 8;
        main_kernel<<<blocks, threads>>>(x, out, B);
    }
}

// round 11
// speedup vs baseline: 2.1324x; 1.0083x over previous
#include <cuda_runtime.h>
#include <cstdint>

// out[b, 0:128]   = x[b, :]                       for b < B
// out[b, 128:256] = sum_{e: dst[e]==b} x[src[e]]
//
// Pipeline:
//   memset:  zero overflow counter (4-byte graph memset node).
//   K1 bin:  ELL binning, scalar one edge/thread (measured ~3.7us).
//   K2 main: R4/R10-exact gather loop (measured ~27us; ptxas batches the
//            loads — do not restructure). g_cnt self-cleaned AFTER the
//            output stores (a pre-loop store measurably destroys the
//            loop's load batching; a trailing store only orders
//            loads-before-store and is benign). Replaces the 4.1us
//            zero_cnt kernel.

#define NFEAT   128
#define ROW_OUT 256
#define MAX_E   640000
#define B_MAX   65536
#define SLOTS   32

__device__ int  g_cnt[B_MAX];
__device__ int  g_ell[B_MAX * SLOTS];
__device__ int2 g_ovf[MAX_E];
__device__ int  g_ovf_count;

__global__ void bin_kernel(const int* __restrict__ ei, int E, int B) {
    int i = blockIdx.x * blockDim.x + threadIdx.x;
    if (i >= E) return;
    int d = __ldg(ei + E + i);
    if ((unsigned)d < (unsigned)B) {
        int s = __ldg(ei + i);
        int k = atomicAdd(&g_cnt[d], 1);
        if (k < SLOTS) {
            g_ell[d * SLOTS + k] = s;
        } else {
            int p = atomicAdd(&g_ovf_count, 1);
            g_ovf[p] = make_int2(s, d);
        }
    }
}

__global__ void main_kernel(const float* __restrict__ x,
                            float* __restrict__ out,
                            int B) {
    int warp = (blockIdx.x * blockDim.x + threadIdx.x) >> 5;
    int lane = threadIdx.x & 31;
    if (warp >= B) return;
    int b = warp;

    int c_raw = g_cnt[b];
    int c = c_raw < SLOTS ? c_raw : SLOTS;

    // Coalesced preload of this row's source list (one slot per lane).
    int src_l = (lane < c) ? g_ell[b * SLOTS + lane] : 0;

    float4 acc = make_float4(0.f, 0.f, 0.f, 0.f);
    for (int k = 0; k < c; k++) {
        int se = __shfl_sync(0xFFFFFFFFu, src_l, k);
        float4 v = __ldg(reinterpret_cast<const float4*>(
                             x + (size_t)se * NFEAT) + lane);
        acc.x += v.x; acc.y += v.y; acc.z += v.z; acc.w += v.w;
    }

    // Rare path: degree exceeded SLOTS -> extras live in the overflow list.
    if (c_raw > SLOTS) {
        int n = g_ovf_count;
        for (int e = 0; e < n; e++) {
            int2 ed = g_ovf[e];
            if (ed.y == b) {
                float4 v = __ldg(reinterpret_cast<const float4*>(
                                     x + (size_t)ed.x * NFEAT) + lane);
                acc.x += v.x; acc.y += v.y; acc.z += v.z; acc.w += v.w;
            }
        }
    }

    // Fused: first half = x[b], second half = neighbor sum.
    float4 mine = __ldg(reinterpret_cast<const float4*>(
                            x + (size_t)b * NFEAT) + lane);
    float4* orow = reinterpret_cast<float4*>(out + (size_t)b * ROW_OUT);
    orow[lane]               = mine;
    orow[(NFEAT / 4) + lane] = acc;

    // Self-clean AFTER all loop loads and output stores (trailing store:
    // benign for scheduling; replaces the zero_cnt kernel).
    if (lane == 0) g_cnt[b] = 0;
}

extern "C" void kernel_launch(void* const* d_in, const int* in_sizes, int n_in,
                              void* d_out, int out_size) {
    const float* x        = (const float*)d_in[0];
    const int*   edge_idx = (const int*)d_in[1];
    float*       out      = (float*)d_out;

    int B = out_size / ROW_OUT;          // 50000
    int E = in_sizes[1] / 2;             // 640000

    // Zero the 4-byte overflow counter via a graph memset node.
    void* p_ovfc = nullptr;
    cudaGetSymbolAddress(&p_ovfc, g_ovf_count);
    cudaMemsetAsync(p_ovfc, 0, sizeof(int));

    {   // K1: ELL binning (one edge per thread)
        int threads = 256;
        int blocks = (E + threads - 1) / threads;
        bin_kernel<<<blocks, threads>>>(edge_idx, E, B);
    }
    {   // K2: main fused gather-accumulate-store, one full warp per row
        int threads = 256;                          // 8 warps/block
        int blocks = (B + 7) / 8;
        main_kernel<<<blocks, threads>>>(x, out, B);
    }
}

// round 12
// speedup vs baseline: 2.2338x; 1.0475x over previous
#include <cuda_runtime.h>
#include <cstdint>

// out[b, 0:128]   = x[b, :]                       for b < B
// out[b, 128:256] = sum_{e: dst[e]==b} x[src[e]]
//
// Pipeline (2 graph nodes, PDL-overlapped):
//   K1 bin:  ELL binning, scalar one edge/thread; triggers programmatic
//            launch completion so main can ramp up concurrently.
//   K2 main: launched with ProgrammaticStreamSerialization; first statement
//            is cudaGridDependencySynchronize(), then the R11-exact body
//            (gather loop untouched — ptxas load batching is fragile:
//            any store BEFORE the loop destroys it; trailing stores are
//            benign, measured). Self-cleans g_cnt AND g_ovf_count after
//            the output stores, so no memset node is needed.

#define NFEAT   128
#define ROW_OUT 256
#define MAX_E   640000
#define B_MAX   65536
#define SLOTS   32

__device__ int  g_cnt[B_MAX];
__device__ int  g_ell[B_MAX * SLOTS];
__device__ int2 g_ovf[MAX_E];
__device__ int  g_ovf_count;

__global__ void bin_kernel(const int* __restrict__ ei, int E, int B) {
    int i = blockIdx.x * blockDim.x + threadIdx.x;
    if (i < E) {
        int d = __ldg(ei + E + i);
        if ((unsigned)d < (unsigned)B) {
            int s = __ldg(ei + i);
            int k = atomicAdd(&g_cnt[d], 1);
            if (k < SLOTS) {
                g_ell[d * SLOTS + k] = s;
            } else {
                int p = atomicAdd(&g_ovf_count, 1);
                g_ovf[p] = make_int2(s, d);
            }
        }
    }
    // Allow the dependent main_kernel to begin its launch ramp.
    cudaTriggerProgrammaticLaunchCompletion();
}

__global__ void main_kernel(const float* __restrict__ x,
                            float* __restrict__ out,
                            int B) {
    // Block until bin_kernel's results (g_cnt/g_ell/g_ovf) are visible.
    cudaGridDependencySynchronize();

    int warp = (blockIdx.x * blockDim.x + threadIdx.x) >> 5;
    int lane = threadIdx.x & 31;
    if (warp >= B) return;
    int b = warp;

    int c_raw = g_cnt[b];
    int c = c_raw < SLOTS ? c_raw : SLOTS;

    // Coalesced preload of this row's source list (one slot per lane).
    int src_l = (lane < c) ? g_ell[b * SLOTS + lane] : 0;

    float4 acc = make_float4(0.f, 0.f, 0.f, 0.f);
    for (int k = 0; k < c; k++) {
        int se = __shfl_sync(0xFFFFFFFFu, src_l, k);
        float4 v = __ldg(reinterpret_cast<const float4*>(
                             x + (size_t)se * NFEAT) + lane);
        acc.x += v.x; acc.y += v.y; acc.z += v.z; acc.w += v.w;
    }

    // Rare path: degree exceeded SLOTS -> extras live in the overflow list.
    if (c_raw > SLOTS) {
        int n = g_ovf_count;
        for (int e = 0; e < n; e++) {
            int2 ed = g_ovf[e];
            if (ed.y == b) {
                float4 v = __ldg(reinterpret_cast<const float4*>(
                                     x + (size_t)ed.x * NFEAT) + lane);
                acc.x += v.x; acc.y += v.y; acc.z += v.z; acc.w += v.w;
            }
        }
    }

    // Fused: first half = x[b], second half = neighbor sum.
    float4 mine = __ldg(reinterpret_cast<const float4*>(
                            x + (size_t)b * NFEAT) + lane);
    float4* orow = reinterpret_cast<float4*>(out + (size_t)b * ROW_OUT);
    orow[lane]               = mine;
    orow[(NFEAT / 4) + lane] = acc;

    // Trailing self-clean (measured benign): restores all counters for the
    // next graph replay, eliminating the memset node.
    if (lane == 0) g_cnt[b] = 0;
    if (b == 0 && lane == 0) g_ovf_count = 0;
}

extern "C" void kernel_launch(void* const* d_in, const int* in_sizes, int n_in,
                              void* d_out, int out_size) {
    const float* x        = (const float*)d_in[0];
    const int*   edge_idx = (const int*)d_in[1];
    float*       out      = (float*)d_out;

    int B = out_size / ROW_OUT;          // 50000
    int E = in_sizes[1] / 2;             // 640000

    {   // K1: ELL binning (one edge per thread)
        int threads = 256;
        int blocks = (E + threads - 1) / threads;
        bin_kernel<<<blocks, threads>>>(edge_idx, E, B);
    }
    {   // K2: main, PDL-overlapped with bin's tail
        int threads = 256;                          // 8 warps/block
        int blocks = (B + 7) / 8;

        cudaLaunchConfig_t cfg = {};
        cfg.gridDim  = dim3(blocks, 1, 1);
        cfg.blockDim = dim3(threads, 1, 1);
        cfg.dynamicSmemBytes = 0;
        cfg.stream = 0;
        cudaLaunchAttribute attrs[1];
        attrs[0].id = cudaLaunchAttributeProgrammaticStreamSerialization;
        attrs[0].val.programmaticStreamSerializationAllowed = 1;
        cfg.attrs = attrs;
        cfg.numAttrs = 1;
        cudaLaunchKernelEx(&cfg, main_kernel, x, out, B);
    }
}